// round 12
// baseline (speedup 1.0000x reference)
#include <cuda_runtime.h>
#include <cuda_bf16.h>
#include <stdint.h>

#define THREADS 256
#define ITEMS   8
#define CHUNK   (THREADS * ITEMS)   // 2048
#define NWARPS  (THREADS / 32)      // 8

__global__ __launch_bounds__(THREADS, 2)
void traj_scan_kernel(const int*   __restrict__ states,
                      const float* __restrict__ e0s,
                      const float* __restrict__ speed0,
                      const float* __restrict__ speed1,
                      const float* __restrict__ x0,
                      float*       __restrict__ X,
                      int T, int P)
{
    __shared__ float4 s_t[2][NWARPS][2];   // parity-buffered 8-comp warp totals

    const int b = blockIdx.x;
    const int*   srow = states + (size_t)b * T;
    const float* erow = e0s    + (size_t)b * (T + 1) * 3;
    float*       xrow = X      + (size_t)b * T * 3;

    const float sp0 = speed0[b], sp1 = speed1[b];
    const float ox = x0[3 * b + 0], oy = x0[3 * b + 1], oz = x0[3 * b + 2];
    const float DT = 0.1f;

    const int tid = threadIdx.x, lane = tid & 31, wid = tid >> 5;

    // ---- load 8 states of chunk c (pad state 1 = non-tumble, speed1) ----
    #define LDST(c, A, B) do {                                                \
        const int _t0 = (c) * CHUNK + tid * ITEMS;                            \
        if (_t0 + ITEMS <= T) {                                               \
            A = *reinterpret_cast<const int4*>(srow + _t0);                   \
            B = *reinterpret_cast<const int4*>(srow + _t0 + 4);               \
        } else {                                                              \
            int _s[8] = {1,1,1,1,1,1,1,1};                                    \
            _Pragma("unroll")                                                 \
            for (int _i = 0; _i < ITEMS; _i++)                                \
                if (_t0 + _i < T) _s[_i] = srow[_t0 + _i];                    \
            A = make_int4(_s[0], _s[1], _s[2], _s[3]);                        \
            B = make_int4(_s[4], _s[5], _s[6], _s[7]);                        \
        } } while (0)

    // ---- pack (tb | s0<<8 | zm<<16) into one word ----
    #define MKMASK(A, B, c, M) do {                                           \
        const int _t0 = (c) * CHUNK + tid * ITEMS;                            \
        const int _s[8] = {A.x, A.y, A.z, A.w, B.x, B.y, B.z, B.w};           \
        unsigned _tb = 0, _s0 = 0, _zm = 0;                                   \
        _Pragma("unroll")                                                     \
        for (int _i = 0; _i < ITEMS; _i++) {                                  \
            const unsigned _isT = (_s[_i] == 2);                              \
            const unsigned _inv = (_t0 + _i >= T);                            \
            _tb |= _isT << _i;                                                \
            _s0 |= (unsigned)(_s[_i] == 0) << _i;                             \
            _zm |= (_isT | _inv) << _i;                                       \
        }                                                                     \
        M = _tb | (_s0 << 8) | (_zm << 16); } while (0)

    #define ISSUE(kb, M, g) do {                                              \
        const unsigned _tb = (M) & 0xffu;                                     \
        _Pragma("unroll")                                                     \
        for (int _i = 0; _i < ITEMS; _i++) {                                  \
            const int _k = (kb) + __popc(_tb & ((2u << _i) - 1u));            \
            const float* _e = erow + (size_t)_k * 3;                          \
            g[3*_i+0] = __ldg(_e + 0);                                        \
            g[3*_i+1] = __ldg(_e + 1);                                        \
            g[3*_i+2] = __ldg(_e + 2);                                        \
        } } while (0)

    #define CONSUME(M, g, vx, vy, vz, ax, ay, az) do {                        \
        const unsigned _s0 = ((M) >> 8) & 0xffu, _zm = ((M) >> 16) & 0xffu;   \
        ax = 0.f; ay = 0.f; az = 0.f;                                         \
        _Pragma("unroll")                                                     \
        for (int _i = 0; _i < ITEMS; _i++) {                                  \
            const float _sp = ((_zm >> _i) & 1u) ? 0.f                        \
                            : (((_s0 >> _i) & 1u) ? sp0 : sp1);               \
            ax = fmaf(g[3*_i+0], _sp, ax);                                    \
            ay = fmaf(g[3*_i+1], _sp, ay);                                    \
            az = fmaf(g[3*_i+2], _sp, az);                                    \
            vx[_i] = ax; vy[_i] = ay; vz[_i] = az;                            \
        } } while (0)

    #define STORE_CHUNK(c, vx, vy, vz, ex, ey, ez) do {                       \
        const int _t0 = (c) * CHUNK + tid * ITEMS;                            \
        const float _bx = fmaf(DT, ex, ox);                                   \
        const float _by = fmaf(DT, ey, oy);                                   \
        const float _bz = fmaf(DT, ez, oz);                                   \
        if (_t0 + ITEMS <= T) {                                               \
            float4* _q = reinterpret_cast<float4*>(xrow + (size_t)_t0 * 3);   \
            _Pragma("unroll")                                                 \
            for (int _g = 0; _g < 6; _g++) {                                  \
                float _o[4];                                                  \
                _Pragma("unroll")                                             \
                for (int _j = 0; _j < 4; _j++) {                              \
                    const int _f = _g * 4 + _j, _it = _f / 3, _d = _f % 3;    \
                    const float _bc = (_d==0) ? _bx : (_d==1) ? _by : _bz;    \
                    const float _vc = (_d==0) ? vx[_it]                       \
                                    : (_d==1) ? vy[_it] : vz[_it];            \
                    _o[_j] = fmaf(DT, _vc, _bc);                              \
                }                                                             \
                __stwt(_q + _g, make_float4(_o[0], _o[1], _o[2], _o[3]));     \
            }                                                                 \
        } else {                                                              \
            _Pragma("unroll")                                                 \
            for (int _i = 0; _i < ITEMS; _i++) {                              \
                if (_t0 + _i < T) {                                           \
                    float* _o = xrow + (size_t)(_t0 + _i) * 3;                \
                    _o[0] = fmaf(DT, vx[_i], _bx);                            \
                    _o[1] = fmaf(DT, vy[_i], _by);                            \
                    _o[2] = fmaf(DT, vz[_i], _bz);                            \
                }                                                             \
            }                                                                 \
        } } while (0)

    // ================= prologue: masks 0..3, issue chunks 0,1 ==============
    unsigned m0, m1, m2, m3;
    {
        int4 A, B;
        LDST(0, A, B); MKMASK(A, B, 0, m0);
        LDST(1, A, B); MKMASK(A, B, 1, m1);
        LDST(2, A, B); MKMASK(A, B, 2, m2);
        LDST(3, A, B); MKMASK(A, B, 3, m3);
    }

    float ga[24], gb[24];
    int K;
    {
        const int c0 = __popc(m0 & 0xffu), c1 = __popc(m1 & 0xffu);
        int a0 = c0, a1 = c1;
        #pragma unroll
        for (int d = 1; d < 32; d <<= 1) {
            const int y0 = __shfl_up_sync(0xffffffffu, a0, d);
            const int y1 = __shfl_up_sync(0xffffffffu, a1, d);
            if (lane >= d) { a0 += y0; a1 += y1; }
        }
        if (lane == 31)
            s_t[0][wid][0] = make_float4((float)a0, (float)a1, 0.f, 0.f);
        __syncthreads();
        int w0e = 0, t0s = 0, w1e = 0, t1s = 0;
        #pragma unroll
        for (int j = 0; j < NWARPS; j++) {
            const float4 t = s_t[0][j][0];
            const int v0 = (int)t.x, v1 = (int)t.y;
            if (j < wid) { w0e += v0; w1e += v1; }
            t0s += v0; t1s += v1;
        }
        ISSUE(w0e + (a0 - c0), m0, ga);
        if (P > 1) ISSUE(t0s + w1e + (a1 - c1), m1, gb);
        K = t0s + t1s;                     // tumbles through chunk 1
        __syncthreads();                   // protect s_t before body writes
    }

    float cx = 0.f, cy = 0.f, cz = 0.f;
    int parity = 0;

    // ============ main loop: 2 chunks per body, ONE barrier per body ========
    for (int i = 0; i < P; i += 2, parity ^= 1) {
        // early state loads for chunks i+4, i+5 (converted at body bottom)
        int4 pa, pb, qa, qb;
        const bool h4 = (i + 4) < P, h5 = (i + 5) < P;
        if (h4) LDST(i + 4, pa, pb);
        if (h5) LDST(i + 5, qa, qb);

        // ---- consume BOTH chunks at body top ----
        float v1x[ITEMS], v1y[ITEMS], v1z[ITEMS], a1x, a1y, a1z;
        CONSUME(m0, ga, v1x, v1y, v1z, a1x, a1y, a1z);

        float v2x[ITEMS], v2y[ITEMS], v2z[ITEMS], a2x, a2y, a2z;
        if (i + 1 < P) {
            CONSUME(m1, gb, v2x, v2y, v2z, a2x, a2y, a2z);
        } else {
            a2x = a2y = a2z = 0.f;
            #pragma unroll
            for (int j = 0; j < ITEMS; j++) { v2x[j]=0.f; v2y[j]=0.f; v2z[j]=0.f; }
        }

        // ---- single fused 8-component scan ----
        const int c2 = __popc(m2 & 0xffu), c3 = __popc(m3 & 0xffu);
        float s1x = a1x, s1y = a1y, s1z = a1z, sr2 = (float)c2;
        float s2x = a2x, s2y = a2y, s2z = a2z, sr3 = (float)c3;
        #pragma unroll
        for (int d = 1; d < 32; d <<= 1) {
            const float u0 = __shfl_up_sync(0xffffffffu, s1x, d);
            const float u1 = __shfl_up_sync(0xffffffffu, s1y, d);
            const float u2 = __shfl_up_sync(0xffffffffu, s1z, d);
            const float u3 = __shfl_up_sync(0xffffffffu, sr2, d);
            const float u4 = __shfl_up_sync(0xffffffffu, s2x, d);
            const float u5 = __shfl_up_sync(0xffffffffu, s2y, d);
            const float u6 = __shfl_up_sync(0xffffffffu, s2z, d);
            const float u7 = __shfl_up_sync(0xffffffffu, sr3, d);
            if (lane >= d) {
                s1x += u0; s1y += u1; s1z += u2; sr2 += u3;
                s2x += u4; s2y += u5; s2z += u6; sr3 += u7;
            }
        }
        if (lane == 31) {
            s_t[parity][wid][0] = make_float4(s1x, s1y, s1z, sr2);
            s_t[parity][wid][1] = make_float4(s2x, s2y, s2z, sr3);
        }
        __syncthreads();                   // the ONLY barrier this body

        float w1xe=0.f, w1ye=0.f, w1ze=0.f, wr2e=0.f;
        float w2xe=0.f, w2ye=0.f, w2ze=0.f, wr3e=0.f;
        float t1xs=0.f, t1ys=0.f, t1zs=0.f, tr2s=0.f;
        float t2xs=0.f, t2ys=0.f, t2zs=0.f, tr3s=0.f;
        #pragma unroll
        for (int j = 0; j < NWARPS; j++) {
            const float4 t0 = s_t[parity][j][0];
            const float4 t1 = s_t[parity][j][1];
            if (j < wid) {
                w1xe += t0.x; w1ye += t0.y; w1ze += t0.z; wr2e += t0.w;
                w2xe += t1.x; w2ye += t1.y; w2ze += t1.z; wr3e += t1.w;
            }
            t1xs += t0.x; t1ys += t0.y; t1zs += t0.z; tr2s += t0.w;
            t2xs += t1.x; t2ys += t1.y; t2zs += t1.z; tr3s += t1.w;
        }
        // chunk i exclusive base
        const float e1x = cx + w1xe + (s1x - a1x);
        const float e1y = cy + w1ye + (s1y - a1y);
        const float e1z = cz + w1ze + (s1z - a1z);
        // chunk i+1 exclusive base = carry + total(chunk i) + warp/thread excl
        const float e2x = cx + t1xs + w2xe + (s2x - a2x);
        const float e2y = cy + t1ys + w2ye + (s2y - a2y);
        const float e2z = cz + t1zs + w2ze + (s2z - a2z);
        // tumble bases for chunks i+2, i+3
        const int kb2 = K + (int)wr2e + (int)(sr2 - (float)c2);
        const int kb3 = K + (int)tr2s + (int)wr3e + (int)(sr3 - (float)c3);
        cx += t1xs + t2xs; cy += t1ys + t2ys; cz += t1zs + t2zs;
        K  += (int)tr2s + (int)tr3s;

        // ---- issue gathers for chunks i+2, i+3; stores interleaved ----
        if (i + 2 < P) ISSUE(kb2, m2, ga);
        STORE_CHUNK(i, v1x, v1y, v1z, e1x, e1y, e1z);
        if (i + 3 < P) ISSUE(kb3, m3, gb);
        if (i + 1 < P) STORE_CHUNK(i + 1, v2x, v2y, v2z, e2x, e2y, e2z);

        // rotate masks; convert early-loaded states
        m0 = m2; m1 = m3;
        if (h4) MKMASK(pa, pb, i + 4, m2); else m2 = 0x00FF0000u;
        if (h5) MKMASK(qa, qb, i + 5, m3); else m3 = 0x00FF0000u;
    }

    #undef LDST
    #undef MKMASK
    #undef ISSUE
    #undef CONSUME
    #undef STORE_CHUNK
}

extern "C" void kernel_launch(void* const* d_in, const int* in_sizes, int n_in,
                              void* d_out, int out_size)
{
    const int*   states = (const int*)  d_in[0];
    const float* e0s    = (const float*)d_in[1];
    const float* sp0    = (const float*)d_in[2];
    const float* sp1    = (const float*)d_in[3];
    const float* x0     = (const float*)d_in[4];
    float*       X      = (float*)d_out;

    const int B = in_sizes[2];            // speed_0 has B elements
    const int T = in_sizes[0] / B;        // states is (B, T)
    const int P = (T + CHUNK - 1) / CHUNK;

    traj_scan_kernel<<<B, THREADS>>>(states, e0s, sp0, sp1, x0, X, T, P);
}

// round 13
// speedup vs baseline: 1.1239x; 1.1239x over previous
#include <cuda_runtime.h>
#include <cuda_bf16.h>
#include <stdint.h>

#define THREADS 256
#define ITEMS   8
#define CHUNK   (THREADS * ITEMS)   // 2048
#define NWARPS  (THREADS / 32)      // 8

__global__ __launch_bounds__(THREADS, 2)
void traj_scan_kernel(const int*   __restrict__ states,
                      const float* __restrict__ e0s,
                      const float* __restrict__ speed0,
                      const float* __restrict__ speed1,
                      const float* __restrict__ x0,
                      float*       __restrict__ X,
                      int T, int P)
{
    __shared__ float s_a[NWARPS][5];
    __shared__ float s_b[NWARPS][4];

    const int b = blockIdx.x;
    const int*   srow = states + (size_t)b * T;
    const float* erow = e0s    + (size_t)b * (T + 1) * 3;
    float*       xrow = X      + (size_t)b * T * 3;

    const float sp0 = speed0[b], sp1 = speed1[b];
    const float ox = x0[3 * b + 0], oy = x0[3 * b + 1], oz = x0[3 * b + 2];
    const float DT = 0.1f;

    const int tid = threadIdx.x, lane = tid & 31, wid = tid >> 5;

    // ---- load 8 states of chunk c (pad state 1 = non-tumble, speed1) ----
    #define LDST(c, A, B) do {                                                \
        const int _t0 = (c) * CHUNK + tid * ITEMS;                            \
        if (_t0 + ITEMS <= T) {                                               \
            A = *reinterpret_cast<const int4*>(srow + _t0);                   \
            B = *reinterpret_cast<const int4*>(srow + _t0 + 4);               \
        } else {                                                              \
            int _s[8] = {1,1,1,1,1,1,1,1};                                    \
            _Pragma("unroll")                                                 \
            for (int _i = 0; _i < ITEMS; _i++)                                \
                if (_t0 + _i < T) _s[_i] = srow[_t0 + _i];                    \
            A = make_int4(_s[0], _s[1], _s[2], _s[3]);                        \
            B = make_int4(_s[4], _s[5], _s[6], _s[7]);                        \
        } } while (0)

    // ---- pack (tb | s0<<8 | zm<<16) into one word ----
    #define MKMASK(A, B, c, M) do {                                           \
        const int _t0 = (c) * CHUNK + tid * ITEMS;                            \
        const int _s[8] = {A.x, A.y, A.z, A.w, B.x, B.y, B.z, B.w};           \
        unsigned _tb = 0, _s0 = 0, _zm = 0;                                   \
        _Pragma("unroll")                                                     \
        for (int _i = 0; _i < ITEMS; _i++) {                                  \
            const unsigned _isT = (_s[_i] == 2);                              \
            const unsigned _inv = (_t0 + _i >= T);                            \
            _tb |= _isT << _i;                                                \
            _s0 |= (unsigned)(_s[_i] == 0) << _i;                             \
            _zm |= (_isT | _inv) << _i;                                       \
        }                                                                     \
        M = _tb | (_s0 << 8) | (_zm << 16); } while (0)

    #define ISSUE(kb, M, g) do {                                              \
        const unsigned _tb = (M) & 0xffu;                                     \
        _Pragma("unroll")                                                     \
        for (int _i = 0; _i < ITEMS; _i++) {                                  \
            const int _k = (kb) + __popc(_tb & ((2u << _i) - 1u));            \
            const float* _e = erow + (size_t)_k * 3;                          \
            g[3*_i+0] = __ldg(_e + 0);                                        \
            g[3*_i+1] = __ldg(_e + 1);                                        \
            g[3*_i+2] = __ldg(_e + 2);                                        \
        } } while (0)

    // ---- totals only (no prefix arrays -> 24 fewer live registers) ----
    #define CONSUME_TOT(M, g, ax, ay, az) do {                                \
        const unsigned _s0 = ((M) >> 8) & 0xffu, _zm = ((M) >> 16) & 0xffu;   \
        ax = 0.f; ay = 0.f; az = 0.f;                                         \
        _Pragma("unroll")                                                     \
        for (int _i = 0; _i < ITEMS; _i++) {                                  \
            const float _sp = ((_zm >> _i) & 1u) ? 0.f                        \
                            : (((_s0 >> _i) & 1u) ? sp0 : sp1);               \
            ax = fmaf(g[3*_i+0], _sp, ax);                                    \
            ay = fmaf(g[3*_i+1], _sp, ay);                                    \
            az = fmaf(g[3*_i+2], _sp, az);                                    \
        } } while (0)

    // ---- store: recompute running prefix from g + mask, starting at ex ----
    #define STORE_CHUNK(c, M, g, ex, ey, ez) do {                             \
        const int _t0 = (c) * CHUNK + tid * ITEMS;                            \
        const unsigned _s0 = ((M) >> 8) & 0xffu, _zm = ((M) >> 16) & 0xffu;   \
        float _rx = (ex), _ry = (ey), _rz = (ez);                             \
        if (_t0 + ITEMS <= T) {                                               \
            float4* _q = reinterpret_cast<float4*>(xrow + (size_t)_t0 * 3);   \
            float _o[24];                                                     \
            _Pragma("unroll")                                                 \
            for (int _i = 0; _i < ITEMS; _i++) {                              \
                const float _sp = ((_zm >> _i) & 1u) ? 0.f                    \
                                : (((_s0 >> _i) & 1u) ? sp0 : sp1);           \
                _rx = fmaf(g[3*_i+0], _sp, _rx);                              \
                _ry = fmaf(g[3*_i+1], _sp, _ry);                              \
                _rz = fmaf(g[3*_i+2], _sp, _rz);                              \
                _o[3*_i+0] = fmaf(DT, _rx, ox);                               \
                _o[3*_i+1] = fmaf(DT, _ry, oy);                               \
                _o[3*_i+2] = fmaf(DT, _rz, oz);                               \
            }                                                                 \
            _Pragma("unroll")                                                 \
            for (int _g2 = 0; _g2 < 6; _g2++)                                 \
                __stwt(_q + _g2, make_float4(_o[4*_g2+0], _o[4*_g2+1],        \
                                             _o[4*_g2+2], _o[4*_g2+3]));      \
        } else {                                                              \
            _Pragma("unroll")                                                 \
            for (int _i = 0; _i < ITEMS; _i++) {                              \
                const float _sp = ((_zm >> _i) & 1u) ? 0.f                    \
                                : (((_s0 >> _i) & 1u) ? sp0 : sp1);           \
                _rx = fmaf(g[3*_i+0], _sp, _rx);                              \
                _ry = fmaf(g[3*_i+1], _sp, _ry);                              \
                _rz = fmaf(g[3*_i+2], _sp, _rz);                              \
                if (_t0 + _i < T) {                                           \
                    float* _p = xrow + (size_t)(_t0 + _i) * 3;                \
                    _p[0] = fmaf(DT, _rx, ox);                                \
                    _p[1] = fmaf(DT, _ry, oy);                                \
                    _p[2] = fmaf(DT, _rz, oz);                                \
                }                                                             \
            }                                                                 \
        } } while (0)

    // ================= prologue: masks 0..3, issue chunks 0,1 ==============
    unsigned m0, m1, m2, m3;
    {
        int4 A, B;
        LDST(0, A, B); MKMASK(A, B, 0, m0);
        LDST(1, A, B); MKMASK(A, B, 1, m1);
        LDST(2, A, B); MKMASK(A, B, 2, m2);
        LDST(3, A, B); MKMASK(A, B, 3, m3);
    }

    float ga[24], gb[24];
    int K;
    {
        const int c0 = __popc(m0 & 0xffu), c1 = __popc(m1 & 0xffu);
        int a0 = c0, a1 = c1;
        #pragma unroll
        for (int d = 1; d < 32; d <<= 1) {
            const int y0 = __shfl_up_sync(0xffffffffu, a0, d);
            const int y1 = __shfl_up_sync(0xffffffffu, a1, d);
            if (lane >= d) { a0 += y0; a1 += y1; }
        }
        if (lane == 31) { s_a[wid][0] = (float)a0; s_a[wid][1] = (float)a1; }
        __syncthreads();
        int w0e = 0, t0s = 0, w1e = 0, t1s = 0;
        #pragma unroll
        for (int j = 0; j < NWARPS; j++) {
            const int v0 = (int)s_a[j][0], v1 = (int)s_a[j][1];
            if (j < wid) { w0e += v0; w1e += v1; }
            t0s += v0; t1s += v1;
        }
        ISSUE(w0e + (a0 - c0), m0, ga);
        if (P > 1) ISSUE(t0s + w1e + (a1 - c1), m1, gb);
        K = t0s + t1s;                     // tumbles through chunk 1
        __syncthreads();                   // protect s_a before body writes
    }

    float cx = 0.f, cy = 0.f, cz = 0.f;

    // ================= main loop: two chunks per body =======================
    for (int i = 0; i < P; i += 2) {
        // early state loads for chunks i+4, i+5 (converted at body bottom)
        int4 pa, pb, qa, qb;
        const bool h4 = (i + 4) < P, h5 = (i + 5) < P;
        if (h4) LDST(i + 4, pa, pb);
        if (h5) LDST(i + 5, qa, qb);

        // ---------- first half: chunk i ----------
        float ax, ay, az;
        CONSUME_TOT(m0, ga, ax, ay, az);

        const int c2 = __popc(m2 & 0xffu), c3 = __popc(m3 & 0xffu);
        float sx = ax, sy = ay, sz = az, s2 = (float)c2, s3 = (float)c3;
        #pragma unroll
        for (int d = 1; d < 32; d <<= 1) {
            const float tx = __shfl_up_sync(0xffffffffu, sx, d);
            const float ty = __shfl_up_sync(0xffffffffu, sy, d);
            const float tz = __shfl_up_sync(0xffffffffu, sz, d);
            const float u2 = __shfl_up_sync(0xffffffffu, s2, d);
            const float u3 = __shfl_up_sync(0xffffffffu, s3, d);
            if (lane >= d) { sx += tx; sy += ty; sz += tz; s2 += u2; s3 += u3; }
        }
        if (lane == 31) {
            s_a[wid][0] = sx; s_a[wid][1] = sy; s_a[wid][2] = sz;
            s_a[wid][3] = s2; s_a[wid][4] = s3;
        }
        __syncthreads();
        float wxe = 0.f, wye = 0.f, wze = 0.f, txs = 0.f, tys = 0.f, tzs = 0.f;
        int wre2 = 0, tot2 = 0, wre3 = 0, tot3 = 0;
        #pragma unroll
        for (int j = 0; j < NWARPS; j++) {
            const float fx = s_a[j][0], fy = s_a[j][1], fz = s_a[j][2];
            const int   i2 = (int)s_a[j][3], i3 = (int)s_a[j][4];
            if (j < wid) { wxe += fx; wye += fy; wze += fz; wre2 += i2; wre3 += i3; }
            txs += fx; tys += fy; tzs += fz; tot2 += i2; tot3 += i3;
        }
        const float ex = cx + wxe + (sx - ax);
        const float ey = cy + wye + (sy - ay);
        const float ez = cz + wze + (sz - az);
        const int kb2 = K + wre2 + ((int)s2 - c2);
        const int kb3 = K + tot2 + wre3 + ((int)s3 - c3);
        cx += txs; cy += tys; cz += tzs;
        K += tot2 + tot3;

        // store chunk i first (frees nothing but overlaps), then refill ga
        STORE_CHUNK(i, m0, ga, ex, ey, ez);
        if (i + 2 < P) ISSUE(kb2, m2, ga);      // flies ~2 chunk-times

        // ---------- second half: chunk i+1 ----------
        if (i + 1 < P) {
            float bx, by, bz;
            CONSUME_TOT(m1, gb, bx, by, bz);

            float tx2 = bx, ty2 = by, tz2 = bz;
            #pragma unroll
            for (int d = 1; d < 32; d <<= 1) {
                const float ux = __shfl_up_sync(0xffffffffu, tx2, d);
                const float uy = __shfl_up_sync(0xffffffffu, ty2, d);
                const float uz = __shfl_up_sync(0xffffffffu, tz2, d);
                if (lane >= d) { tx2 += ux; ty2 += uy; tz2 += uz; }
            }
            if (lane == 31) {
                s_b[wid][0] = tx2; s_b[wid][1] = ty2; s_b[wid][2] = tz2;
            }
            __syncthreads();
            float wx2 = 0.f, wy2 = 0.f, wz2 = 0.f, tx2s = 0.f, ty2s = 0.f, tz2s = 0.f;
            #pragma unroll
            for (int j = 0; j < NWARPS; j++) {
                const float fx = s_b[j][0], fy = s_b[j][1], fz = s_b[j][2];
                if (j < wid) { wx2 += fx; wy2 += fy; wz2 += fz; }
                tx2s += fx; ty2s += fy; tz2s += fz;
            }
            const float ex2 = cx + wx2 + (tx2 - bx);
            const float ey2 = cy + wy2 + (ty2 - by);
            const float ez2 = cz + wz2 + (tz2 - bz);
            cx += tx2s; cy += ty2s; cz += tz2s;

            STORE_CHUNK(i + 1, m1, gb, ex2, ey2, ez2);
            if (i + 3 < P) ISSUE(kb3, m3, gb);
        }

        // rotate masks; convert early-loaded states
        m0 = m2; m1 = m3;
        if (h4) MKMASK(pa, pb, i + 4, m2); else m2 = 0x00FF0000u;
        if (h5) MKMASK(qa, qb, i + 5, m3); else m3 = 0x00FF0000u;
    }

    #undef LDST
    #undef MKMASK
    #undef ISSUE
    #undef CONSUME_TOT
    #undef STORE_CHUNK
}

extern "C" void kernel_launch(void* const* d_in, const int* in_sizes, int n_in,
                              void* d_out, int out_size)
{
    const int*   states = (const int*)  d_in[0];
    const float* e0s    = (const float*)d_in[1];
    const float* sp0    = (const float*)d_in[2];
    const float* sp1    = (const float*)d_in[3];
    const float* x0     = (const float*)d_in[4];
    float*       X      = (float*)d_out;

    const int B = in_sizes[2];            // speed_0 has B elements
    const int T = in_sizes[0] / B;        // states is (B, T)
    const int P = (T + CHUNK - 1) / CHUNK;

    traj_scan_kernel<<<B, THREADS>>>(states, e0s, sp0, sp1, x0, X, T, P);
}